// round 1
// baseline (speedup 1.0000x reference)
#include <cuda_runtime.h>
#include <cstdint>
#include <math.h>

#define S16 16
#define MAXB 128
#define MAXT 2048
#define MAXNC 64
#define CHUNK_L 50

// ---------------- device scratch (static, no allocation) ----------------
__device__ float g_Bexp[(size_t)MAXB * MAXT * S16];      // exp(log_B)
__device__ float g_beta[(size_t)MAXB * MAXT * S16];      // backward vars
__device__ float g_G[(size_t)MAXB * MAXNC * S16 * S16];  // chunk transfer matrices
__device__ float g_abound[MAXB * MAXNC * S16];           // alpha at chunk starts
__device__ float g_bbound[MAXB * MAXNC * S16];           // beta at chunk starts
__device__ float g_P[S16 * S16];
__device__ float g_c1c2[2];
__device__ int   g_structured;

// ---------------- phase 0: copy P, detect structured form ----------------
__global__ void k_prep(const float* __restrict__ P) {
    int i = threadIdx.x;  // 256 threads
    float v = P[i];
    g_P[i] = v;
    float c1 = P[0], c2 = P[1];
    float expd = ((i & 15) == (i >> 4)) ? c1 : c2;
    int ok = (fabsf(v - expd) <= 1e-6f * fabsf(expd) + 1e-30f) ? 1 : 0;
    int all = __syncthreads_and(ok);
    if (i == 0) { g_c1c2[0] = c1; g_c1c2[1] = c2; g_structured = all; }
}

// ---------------- phase 0b: Bexp = exp(log_B) ----------------
__global__ void k_exp(const float4* __restrict__ in, int n4) {
    int i = blockIdx.x * blockDim.x + threadIdx.x;
    if (i < n4) {
        float4 v = in[i];
        float4 r = make_float4(expf(v.x), expf(v.y), expf(v.z), expf(v.w));
        reinterpret_cast<float4*>(g_Bexp)[i] = r;
    }
}

// ---------------- phase 1: per-(batch,chunk) transfer matrix products ----------------
// Unit = 16 lanes; lane i owns row i of M. G_c = prod_{t=s_c+1}^{min(s_{c+1},T-1)} P*diag(B_t)
__global__ void k_chunkprod(int B, int T, int NC) {
    __shared__ float sP[256];
    sP[threadIdx.x] = g_P[threadIdx.x];
    __syncthreads();

    int gtid = blockIdx.x * blockDim.x + threadIdx.x;
    int unit = gtid >> 4;
    int lane = threadIdx.x & 15;
    unsigned hmask = 0xFFFFu << (threadIdx.x & 16);
    if (unit >= B * NC) return;
    int b = unit / NC, c = unit - b * NC;
    int t0 = c * CHUNK_L + 1;
    int t1 = min((c + 1) * CHUNK_L, T - 1);

    const float4* Bx = reinterpret_cast<const float4*>(g_Bexp) + (size_t)b * T * 4;

    float m[16];
#pragma unroll
    for (int k = 0; k < 16; k++) m[k] = (k == lane) ? 1.f : 0.f;

    int str = g_structured;
    float c1 = g_c1c2[0], c2 = g_c1c2[1], dd = c1 - c2;

    int cnt = 0;
    for (int t = t0; t <= t1; t++) {
        float bv[16];
#pragma unroll
        for (int i = 0; i < 4; i++) {
            float4 q = Bx[t * 4 + i];
            bv[4 * i + 0] = q.x; bv[4 * i + 1] = q.y;
            bv[4 * i + 2] = q.z; bv[4 * i + 3] = q.w;
        }
        if (str) {
            float R = 0.f;
#pragma unroll
            for (int k = 0; k < 16; k++) R += m[k];
            float cr = c2 * R;
#pragma unroll
            for (int k = 0; k < 16; k++) m[k] = fmaf(dd, m[k], cr) * bv[k];
        } else {
            float acc[16];
#pragma unroll
            for (int k = 0; k < 16; k++) acc[k] = 0.f;
#pragma unroll
            for (int l = 0; l < 16; l++) {
                float ml = m[l];
#pragma unroll
                for (int k = 0; k < 16; k++)
                    acc[k] = fmaf(ml, sP[l * 16 + k], acc[k]);
            }
#pragma unroll
            for (int k = 0; k < 16; k++) m[k] = acc[k] * bv[k];
        }
        if ((++cnt & 7) == 0) {  // periodic rescale (matrix-uniform scale)
            float mx = m[0];
#pragma unroll
            for (int k = 1; k < 16; k++) mx = fmaxf(mx, m[k]);
#pragma unroll
            for (int o = 1; o < 16; o <<= 1)
                mx = fmaxf(mx, __shfl_xor_sync(hmask, mx, o, 16));
            float inv = 1.f / mx;
#pragma unroll
            for (int k = 0; k < 16; k++) m[k] *= inv;
        }
    }
    // final rescale + store
    float mx = m[0];
#pragma unroll
    for (int k = 1; k < 16; k++) mx = fmaxf(mx, m[k]);
#pragma unroll
    for (int o = 1; o < 16; o <<= 1)
        mx = fmaxf(mx, __shfl_xor_sync(hmask, mx, o, 16));
    float inv = 1.f / mx;
    float4* G4 = reinterpret_cast<float4*>(g_G + (size_t)unit * 256 + lane * 16);
#pragma unroll
    for (int i = 0; i < 4; i++)
        G4[i] = make_float4(m[4 * i + 0] * inv, m[4 * i + 1] * inv,
                            m[4 * i + 2] * inv, m[4 * i + 3] * inv);
}

// ---------------- phase 2: sequential boundary chains (per batch) ----------------
__global__ void k_bound(int B, int T, int NC) {
    int b = blockIdx.x;
    int w = threadIdx.x >> 5;
    int k = threadIdx.x & 15;
    if (w == 0) {
        // forward: alpha_0 ~ B_0 (uniform prior cancels)
        float a = g_Bexp[((size_t)b * T) * 16 + k];
        float s = a;
#pragma unroll
        for (int o = 1; o < 16; o <<= 1) s += __shfl_xor_sync(0xffffffffu, s, o, 16);
        a *= (1.f / s);
        g_abound[(b * NC) * 16 + k] = a;
        for (int c = 0; c < NC - 1; c++) {
            const float* G = g_G + ((size_t)(b * NC + c)) * 256;
            float acc = 0.f;
#pragma unroll
            for (int j = 0; j < 16; j++) {
                float aj = __shfl_sync(0xffffffffu, a, j, 16);
                acc = fmaf(aj, G[j * 16 + k], acc);
            }
            float ss = acc;
#pragma unroll
            for (int o = 1; o < 16; o <<= 1) ss += __shfl_xor_sync(0xffffffffu, ss, o, 16);
            a = acc * (1.f / ss);
            g_abound[(b * NC + c + 1) * 16 + k] = a;
        }
    } else {
        // backward: bbound[NC-1] = G_{NC-1} * 1; then chain down
        const float* G = g_G + ((size_t)(b * NC + NC - 1)) * 256 + k * 16;
        float acc = 0.f;
#pragma unroll
        for (int j = 0; j < 16; j++) acc += G[j];
        float ss = acc;
#pragma unroll
        for (int o = 1; o < 16; o <<= 1) ss += __shfl_xor_sync(0xffffffffu, ss, o, 16);
        float bv = acc * (1.f / ss);
        g_bbound[(b * NC + NC - 1) * 16 + k] = bv;
        for (int c = NC - 2; c >= 0; c--) {
            const float* Gc = g_G + ((size_t)(b * NC + c)) * 256 + k * 16;
            float a2 = 0.f;
#pragma unroll
            for (int j = 0; j < 16; j++) {
                float bj = __shfl_sync(0xffffffffu, bv, j, 16);
                a2 = fmaf(Gc[j], bj, a2);
            }
            ss = a2;
#pragma unroll
            for (int o = 1; o < 16; o <<= 1) ss += __shfl_xor_sync(0xffffffffu, ss, o, 16);
            bv = a2 * (1.f / ss);
            g_bbound[(b * NC + c) * 16 + k] = bv;
        }
    }
}

// ---------------- phase 3a: backward replay, store beta[b,t,:] ----------------
__global__ void k_back(int B, int T, int NC) {
    int gtid = blockIdx.x * blockDim.x + threadIdx.x;
    int unit = gtid >> 4;
    int j = threadIdx.x & 15;
    unsigned hmask = 0xFFFFu << (threadIdx.x & 16);
    if (unit >= B * NC) return;
    int b = unit / NC, c = unit - b * NC;
    int s = c * CHUNK_L;
    int e = min(s + CHUNK_L, T);
    int str = g_structured;
    float c1 = g_c1c2[0], c2 = g_c1c2[1], dd = c1 - c2;
    float prow[16];
    if (!str) {
#pragma unroll
        for (int k = 0; k < 16; k++) prow[k] = g_P[j * 16 + k];
    }
    float beta;
    int tcur;
    if (c == NC - 1) {
        beta = 1.f;
        g_beta[((size_t)b * T + (T - 1)) * 16 + j] = 1.f;
        tcur = T - 1;
    } else {
        beta = g_bbound[(b * NC + c + 1) * 16 + j];
        tcur = e;
    }
    for (int t = tcur - 1; t >= s; t--) {
        float Bn = g_Bexp[((size_t)b * T + t + 1) * 16 + j];
        float w = Bn * beta;
        float W = w;
#pragma unroll
        for (int o = 1; o < 16; o <<= 1) W += __shfl_xor_sync(hmask, W, o, 16);
        float invW = 1.f / W;
        float nb;
        if (str) {
            nb = fmaf(dd, w * invW, c2);
        } else {
            float acc = 0.f;
#pragma unroll
            for (int k = 0; k < 16; k++) {
                float wk = __shfl_sync(hmask, w, k, 16);
                acc = fmaf(prow[k], wk, acc);
            }
            nb = acc * invW;
        }
        g_beta[((size_t)b * T + t) * 16 + j] = nb;
        beta = nb;
    }
}

// ---------------- phase 3b: forward replay + gamma + xi outputs ----------------
// One full warp per (batch,chunk). Lanes 0-15 and 16-31 hold duplicated state
// vectors (width-16 shuffles operate identically in both halves).
__global__ void k_fwd(int B, int T, int NC,
                      float* __restrict__ gamma, float* __restrict__ xi) {
    __shared__ float sP[256];
    sP[threadIdx.x] = g_P[threadIdx.x];
    __syncthreads();

    int warp = (blockIdx.x * blockDim.x + threadIdx.x) >> 5;
    int lane = threadIdx.x & 31;
    int k = lane & 15;
    int half = lane >> 4;
    if (warp >= B * NC) return;
    int b = warp / NC, c = warp - b * NC;
    int s = c * CHUNK_L, e = min(s + CHUNK_L, T);
    int str = g_structured;
    float c1 = g_c1c2[0], c2 = g_c1c2[1], dd = c1 - c2;

    float pcol[16];
    if (!str) {
#pragma unroll
        for (int j = 0; j < 16; j++) pcol[j] = sP[j * 16 + k];
    }

    int jw = lane >> 1;          // xi row this lane writes
    int hk = (lane & 1) * 8;     // xi column base (8 consecutive)

    float alpha = g_abound[(b * NC + c) * 16 + k];
    float beta  = g_beta[((size_t)b * T + s) * 16 + k];
    const float* Bb = g_Bexp + (size_t)b * T * 16;
    const float* Bt = g_beta + (size_t)b * T * 16;

    for (int t = s; t < e; t++) {
        // gamma_t = alpha.*beta / sum
        float ab = alpha * beta;
        float Zg = ab;
#pragma unroll
        for (int o = 1; o < 16; o <<= 1) Zg += __shfl_xor_sync(0xffffffffu, Zg, o, 16);
        if (half == 0)
            gamma[((size_t)b * T + t) * 16 + k] = ab * (1.f / Zg);

        if (t < T - 1) {
            float bn = Bt[(size_t)(t + 1) * 16 + k];
            float Be = Bb[(size_t)(t + 1) * 16 + k];
            float w = Be * bn;
            // u = alpha * P  (column k); alpha sums to 1
            float u;
            if (str) {
                u = fmaf(dd, alpha, c2);
            } else {
                u = 0.f;
#pragma unroll
                for (int j = 0; j < 16; j++) {
                    float aj = __shfl_sync(0xffffffffu, alpha, j, 16);
                    u = fmaf(aj, pcol[j], u);
                }
            }
            float uw = u * w;
            float Zx = uw;
#pragma unroll
            for (int o = 1; o < 16; o <<= 1) Zx += __shfl_xor_sync(0xffffffffu, Zx, o, 16);
            float q = w * (1.f / Zx);

            // xi_t[jw][hk..hk+7] = alpha[jw] * P[jw][kk] * q[kk]
            float aj = __shfl_sync(0xffffffffu, alpha, jw, 16);
            float vals[8];
#pragma unroll
            for (int i = 0; i < 8; i++) {
                int kk = hk + i;
                float qk = __shfl_sync(0xffffffffu, q, kk, 16);
                float pv = str ? ((jw == kk) ? c1 : c2) : sP[jw * 16 + kk];
                vals[i] = aj * pv * qk;
            }
            float4* xo = reinterpret_cast<float4*>(
                xi + ((size_t)b * (T - 1) + t) * 256 + jw * 16 + hk);
            xo[0] = make_float4(vals[0], vals[1], vals[2], vals[3]);
            xo[1] = make_float4(vals[4], vals[5], vals[6], vals[7]);

            // advance alpha
            float an = u * Be;
            float Sn = an;
#pragma unroll
            for (int o = 1; o < 16; o <<= 1) Sn += __shfl_xor_sync(0xffffffffu, Sn, o, 16);
            alpha = an * (1.f / Sn);
            beta = bn;
        }
    }
}

// ---------------- host ----------------
extern "C" void kernel_launch(void* const* d_in, const int* in_sizes, int n_in,
                              void* d_out, int out_size) {
    const float* logB = (const float*)d_in[0];
    const float* P    = (const float*)d_in[1];
    long long nB = in_sizes[0];            // B*T*16
    long long BT = nB / 16;
    long long xiE = (long long)out_size - nB;
    int B = (int)(BT - xiE / 256);
    int T = (int)(BT / B);
    int NC = (T + CHUNK_L - 1) / CHUNK_L;

    float* gamma = (float*)d_out;
    float* xi = gamma + (size_t)B * T * 16;

    k_prep<<<1, 256>>>(P);
    int n4 = (int)(nB / 4);
    k_exp<<<(n4 + 255) / 256, 256>>>((const float4*)logB, n4);
    int units = B * NC;
    k_chunkprod<<<(units * 16 + 255) / 256, 256>>>(B, T, NC);
    k_bound<<<B, 64>>>(B, T, NC);
    k_back<<<(units * 16 + 255) / 256, 256>>>(B, T, NC);
    k_fwd<<<(units * 32 + 255) / 256, 256>>>(B, T, NC, gamma, xi);
    (void)n_in;
}

// round 2
// speedup vs baseline: 1.2801x; 1.2801x over previous
#include <cuda_runtime.h>
#include <math.h>

#define CHUNK_L 50
#define MAXB 128
#define MAXNC 64

// ---------------- device scratch (static) ----------------
__device__ float g_G[(size_t)MAXB * MAXNC * 256];   // chunk transfer matrices (max-normalized)
__device__ float g_abound[MAXB * MAXNC * 16];       // alpha at chunk starts (normalized)
__device__ float g_bbound[MAXB * MAXNC * 16];       // beta at chunk starts (normalized)

// ---------------- helpers ----------------
__device__ __forceinline__ float bflysum16(float v, unsigned mask) {
#pragma unroll
    for (int o = 1; o < 16; o <<= 1) v += __shfl_xor_sync(mask, v, o, 16);
    return v;
}
__device__ __forceinline__ float bflymax16(float v, unsigned mask) {
#pragma unroll
    for (int o = 1; o < 16; o <<= 1) v = fmaxf(v, __shfl_xor_sync(mask, v, o, 16));
    return v;
}
__device__ __forceinline__ float tsum16(const float (&p)[16]) {
    float a0 = (p[0] + p[1]) + (p[2] + p[3]);
    float a1 = (p[4] + p[5]) + (p[6] + p[7]);
    float a2 = (p[8] + p[9]) + (p[10] + p[11]);
    float a3 = (p[12] + p[13]) + (p[14] + p[15]);
    return (a0 + a1) + (a2 + a3);
}
__device__ __forceinline__ float tmax16(const float (&p)[16]) {
    float a0 = fmaxf(fmaxf(p[0], p[1]), fmaxf(p[2], p[3]));
    float a1 = fmaxf(fmaxf(p[4], p[5]), fmaxf(p[6], p[7]));
    float a2 = fmaxf(fmaxf(p[8], p[9]), fmaxf(p[10], p[11]));
    float a3 = fmaxf(fmaxf(p[12], p[13]), fmaxf(p[14], p[15]));
    return fmaxf(fmaxf(a0, a1), fmaxf(a2, a3));
}
// per-warp structured-P detection (all 32 lanes, before any divergence)
__device__ __forceinline__ int detect_str(const float* __restrict__ P, float& c1, float& c2) {
    c1 = __ldg(P); c2 = __ldg(P + 1);
    int lane = threadIdx.x & 31;
    int ok = 1;
#pragma unroll
    for (int i = 0; i < 8; i++) {
        int idx = lane * 8 + i;
        float v = __ldg(P + idx);
        float e = ((idx & 15) == (idx >> 4)) ? c1 : c2;
        ok &= (fabsf(v - e) <= 1e-6f * fabsf(e) + 1e-30f) ? 1 : 0;
    }
    return __all_sync(0xffffffffu, ok);
}

// ---------------- K1: per-(batch,chunk) transfer matrix products ----------------
// 16-lane unit; lane owns row of M. G_c = prod_{t=cL+1}^{min((c+1)L,T-1)} P*diag(exp(logB_t))
__global__ void k_chunkprod(const float* __restrict__ logB, const float* __restrict__ P,
                            int B, int T, int NC) {
    __shared__ float sP[256];
    sP[threadIdx.x] = P[threadIdx.x];   // blockDim == 256
    float c1, c2;
    int str = detect_str(P, c1, c2);
    __syncthreads();
    float dd = c1 - c2;

    int gtid = blockIdx.x * blockDim.x + threadIdx.x;
    int unit = gtid >> 4;
    int lane = threadIdx.x & 15;
    unsigned hmask = 0xFFFFu << (threadIdx.x & 16);
    if (unit >= B * NC) return;
    int b = unit / NC, c = unit - b * NC;
    int t0 = c * CHUNK_L + 1;
    int t1 = min((c + 1) * CHUNK_L, T - 1);
    const float* lb = logB + (size_t)b * T * 16;

    float m[16];
#pragma unroll
    for (int k = 0; k < 16; k++) m[k] = (k == lane) ? 1.f : 0.f;

    float nxt = lb[(size_t)t0 * 16 + lane];
    int cnt = 0;
    for (int t = t0; t <= t1; t++) {
        float bvk = __expf(nxt);
        if (t < t1) nxt = lb[(size_t)(t + 1) * 16 + lane];
        if (str) {
            float R = tsum16(m);
            float cr = c2 * R;
#pragma unroll
            for (int k = 0; k < 16; k++)
                m[k] = fmaf(dd, m[k], cr) * __shfl_sync(0xffffffffu, bvk, k, 16);
        } else {
            float acc[16];
#pragma unroll
            for (int k = 0; k < 16; k++) acc[k] = 0.f;
#pragma unroll
            for (int l = 0; l < 16; l++) {
                float ml = m[l];
#pragma unroll
                for (int k = 0; k < 16; k++) acc[k] = fmaf(ml, sP[l * 16 + k], acc[k]);
            }
#pragma unroll
            for (int k = 0; k < 16; k++)
                m[k] = acc[k] * __shfl_sync(0xffffffffu, bvk, k, 16);
        }
        if ((++cnt & 7) == 0) {   // periodic rescale (uniform matrix scale is harmless)
            float mx = bflymax16(tmax16(m), hmask);
            float inv = __fdividef(1.f, mx);
#pragma unroll
            for (int k = 0; k < 16; k++) m[k] *= inv;
        }
    }
    float mx = bflymax16(tmax16(m), hmask);
    float inv = __fdividef(1.f, mx);
    float4* G4 = reinterpret_cast<float4*>(g_G + (size_t)unit * 256 + lane * 16);
#pragma unroll
    for (int i = 0; i < 4; i++)
        G4[i] = make_float4(m[4 * i] * inv, m[4 * i + 1] * inv,
                            m[4 * i + 2] * inv, m[4 * i + 3] * inv);
}

// ---------------- K2: sequential boundary chains (per batch), prefetched ----------------
__global__ void k_bound(const float* __restrict__ logB, int B, int T, int NC) {
    int b = blockIdx.x;
    int w = threadIdx.x >> 5;
    int lane = threadIdx.x & 31;
    int k = lane & 15;
    const unsigned F = 0xffffffffu;
    const float* Gb = g_G + (size_t)b * NC * 256;

    if (w == 0) {
        // forward: alpha_0 ~ exp(logB_0) (uniform prior cancels)
        float a = __expf(logB[(size_t)b * T * 16 + k]);
        { float Z = bflysum16(a, F); a *= __fdividef(1.f, Z); }
        if (lane < 16) g_abound[(b * NC) * 16 + k] = a;
        if (NC < 2) return;
        float g[16], gn[16];
#pragma unroll
        for (int j = 0; j < 16; j++) g[j] = Gb[j * 16 + k];          // column k of G_0
        for (int c = 0; c < NC - 1; c++) {
            const float* Gn = Gb + (size_t)min(c + 1, NC - 2) * 256;  // prefetch next
#pragma unroll
            for (int j = 0; j < 16; j++) gn[j] = Gn[j * 16 + k];
            float p[16];
#pragma unroll
            for (int j = 0; j < 16; j++) p[j] = __shfl_sync(F, a, j, 16) * g[j];
            float s = tsum16(p);
            float Z = bflysum16(s, F);
            a = s * __fdividef(1.f, Z);
            if (lane < 16) g_abound[(b * NC + c + 1) * 16 + k] = a;
#pragma unroll
            for (int j = 0; j < 16; j++) g[j] = gn[j];
        }
    } else {
        // backward: bbound[NC-1] = normalize(G_{NC-1} * 1); chain down with G_c rows
        float h[16], hn[16];
        {
            const float4* Gr = reinterpret_cast<const float4*>(Gb + (size_t)(NC - 1) * 256 + k * 16);
#pragma unroll
            for (int i = 0; i < 4; i++) {
                float4 q = Gr[i];
                h[4 * i] = q.x; h[4 * i + 1] = q.y; h[4 * i + 2] = q.z; h[4 * i + 3] = q.w;
            }
        }
        float bv = tsum16(h);
        { float Z = bflysum16(bv, F); bv *= __fdividef(1.f, Z); }
        if (lane < 16) g_bbound[(b * NC + NC - 1) * 16 + k] = bv;
        if (NC < 2) return;
        {
            const float4* Gr = reinterpret_cast<const float4*>(Gb + (size_t)(NC - 2) * 256 + k * 16);
#pragma unroll
            for (int i = 0; i < 4; i++) {
                float4 q = Gr[i];
                h[4 * i] = q.x; h[4 * i + 1] = q.y; h[4 * i + 2] = q.z; h[4 * i + 3] = q.w;
            }
        }
        for (int c = NC - 2; c >= 0; c--) {
            const float4* Gr = reinterpret_cast<const float4*>(Gb + (size_t)max(c - 1, 0) * 256 + k * 16);
#pragma unroll
            for (int i = 0; i < 4; i++) {
                float4 q = Gr[i];
                hn[4 * i] = q.x; hn[4 * i + 1] = q.y; hn[4 * i + 2] = q.z; hn[4 * i + 3] = q.w;
            }
            float p[16];
#pragma unroll
            for (int kk = 0; kk < 16; kk++) p[kk] = h[kk] * __shfl_sync(F, bv, kk, 16);
            float s = tsum16(p);
            float Z = bflysum16(s, F);
            bv = s * __fdividef(1.f, Z);
            if (lane < 16) g_bbound[(b * NC + c) * 16 + k] = bv;
#pragma unroll
            for (int kk = 0; kk < 16; kk++) h[kk] = hn[kk];
        }
    }
}

// ---------------- K3: fused backward-replay + forward-replay + gamma + xi ----------------
// One warp per (batch,chunk). Halves duplicate the 16-state vectors.
__global__ void __launch_bounds__(128) k_fused(const float* __restrict__ logB,
                                               const float* __restrict__ P,
                                               int B, int T, int NC,
                                               float* __restrict__ gamma,
                                               float* __restrict__ xi) {
    __shared__ float shB[4][(CHUNK_L + 1) * 16];
    __shared__ float shT[4][(CHUNK_L + 1) * 16];
    __shared__ float sP[256];
    sP[threadIdx.x] = P[threadIdx.x];
    sP[threadIdx.x + 128] = P[threadIdx.x + 128];
    float c1, c2;
    int str = detect_str(P, c1, c2);
    __syncthreads();
    float dd = c1 - c2;
    const unsigned F = 0xffffffffu;

    int wid = threadIdx.x >> 5;
    int lane = threadIdx.x & 31;
    int k = lane & 15;
    int half = lane >> 4;
    int unit = blockIdx.x * 4 + wid;
    if (unit >= B * NC) return;
    int b = unit / NC, c = unit - b * NC;
    int s = c * CHUNK_L, e = min(s + CHUNK_L, T);
    int n = e - s;
    float* Bw = shB[wid];
    float* Tw = shT[wid];

    // ---- phase A: load + exp chunk rows s..min(e,T-1) into shared ----
    int rows = min(e, T - 1) - s + 1;
    const float4* src = reinterpret_cast<const float4*>(logB) + ((size_t)b * T + s) * 4;
    for (int i = lane; i < rows * 4; i += 32) {
        float4 v = src[i];
        reinterpret_cast<float4*>(Bw)[i] =
            make_float4(__expf(v.x), __expf(v.y), __expf(v.z), __expf(v.w));
    }
    __syncwarp();

    // ---- phase B: backward replay into shared ----
    float bcur; int tstart;
    if (c == NC - 1) {
        bcur = 1.f;
        if (half == 0) Tw[(n - 1) * 16 + k] = 1.f;
        tstart = e - 2;
    } else {
        bcur = g_bbound[(b * NC + c + 1) * 16 + k];
        if (half == 0) Tw[n * 16 + k] = bcur;
        tstart = e - 1;
    }
    for (int t = tstart; t >= s; t--) {
        float Bn = Bw[(t + 1 - s) * 16 + k];
        float w = Bn * bcur;
        float W = bflysum16(w, F);
        float iW = __fdividef(1.f, W);
        float nb;
        if (str) {
            nb = fmaf(dd, w * iW, c2);
        } else {
            float acc = 0.f;
#pragma unroll
            for (int kk = 0; kk < 16; kk++)
                acc = fmaf(sP[k * 16 + kk], __shfl_sync(F, w, kk, 16), acc);
            nb = acc * iW;
        }
        if (half == 0) Tw[(t - s) * 16 + k] = nb;
        bcur = nb;
    }
    __syncwarp();

    // ---- phase C: forward replay, emit gamma + xi ----
    float alpha = g_abound[(b * NC + c) * 16 + k];
    { float Z = bflysum16(alpha, F); alpha *= __fdividef(1.f, Z); }
    int jw = lane >> 1;          // xi row this lane writes
    int hk = (lane & 1) * 8;     // xi column base
    float pvv[8];
#pragma unroll
    for (int i = 0; i < 8; i++)
        pvv[i] = str ? ((jw == hk + i) ? c1 : c2) : sP[jw * 16 + hk + i];

    for (int t = s; t < e; t++) {
        float beta = Tw[(t - s) * 16 + k];
        float ab = alpha * beta;
        float Zg = bflysum16(ab, F);
        if (half == 0) gamma[((size_t)b * T + t) * 16 + k] = ab * __fdividef(1.f, Zg);

        if (t < T - 1) {
            float Be = Bw[(t + 1 - s) * 16 + k];
            float bn = Tw[(t + 1 - s) * 16 + k];
            float w = Be * bn;
            float u;
            if (str) {
                u = fmaf(dd, alpha, c2);            // needs sum(alpha)==1 (maintained)
            } else {
                u = 0.f;
#pragma unroll
                for (int j = 0; j < 16; j++)
                    u = fmaf(__shfl_sync(F, alpha, j, 16), sP[j * 16 + k], u);
            }
            float Zx = bflysum16(u * w, F);
            float q = w * __fdividef(1.f, Zx);
            float aj = __shfl_sync(F, alpha, jw, 16);
            float v0[8];
#pragma unroll
            for (int i = 0; i < 8; i++)
                v0[i] = aj * pvv[i] * __shfl_sync(F, q, hk + i, 16);
            float4* xo = reinterpret_cast<float4*>(
                xi + ((size_t)b * (T - 1) + t) * 256 + jw * 16 + hk);
            xo[0] = make_float4(v0[0], v0[1], v0[2], v0[3]);
            xo[1] = make_float4(v0[4], v0[5], v0[6], v0[7]);

            float an = u * Be;
            float Sn = bflysum16(an, F);
            alpha = an * __fdividef(1.f, Sn);
        }
    }
}

// ---------------- host ----------------
extern "C" void kernel_launch(void* const* d_in, const int* in_sizes, int n_in,
                              void* d_out, int out_size) {
    const float* logB = (const float*)d_in[0];
    const float* P    = (const float*)d_in[1];
    long long nB = in_sizes[0];            // B*T*16
    long long BT = nB / 16;
    long long xiE = (long long)out_size - nB;
    int B = (int)(BT - xiE / 256);
    int T = (int)(BT / B);
    int NC = (T + CHUNK_L - 1) / CHUNK_L;

    float* gamma = (float*)d_out;
    float* xi = gamma + (size_t)B * T * 16;

    int units = B * NC;
    k_chunkprod<<<(units * 16 + 255) / 256, 256>>>(logB, P, B, T, NC);
    k_bound<<<B, 64>>>(logB, B, T, NC);
    k_fused<<<(units + 3) / 4, 128>>>(logB, P, B, T, NC, gamma, xi);
    (void)n_in;
}

// round 3
// speedup vs baseline: 1.8963x; 1.4814x over previous
#include <cuda_runtime.h>
#include <math.h>

#define CHUNK_L 25
#define MAXB 128
#define MAXNC 128

// ---------------- device scratch (static) ----------------
__device__ float g_G[(size_t)MAXB * MAXNC * 256];   // chunk transfer matrices (max-normalized)
__device__ float g_abound[MAXB * MAXNC * 16];       // alpha at chunk starts (normalized)
__device__ float g_bbound[MAXB * MAXNC * 16];       // beta at chunk starts (normalized)

// ---------------- helpers ----------------
__device__ __forceinline__ float bflysum16(float v, unsigned mask) {
#pragma unroll
    for (int o = 1; o < 16; o <<= 1) v += __shfl_xor_sync(mask, v, o, 16);
    return v;
}
__device__ __forceinline__ float bflymax16(float v, unsigned mask) {
#pragma unroll
    for (int o = 1; o < 16; o <<= 1) v = fmaxf(v, __shfl_xor_sync(mask, v, o, 16));
    return v;
}
__device__ __forceinline__ float tsum16(const float (&p)[16]) {
    float a0 = (p[0] + p[1]) + (p[2] + p[3]);
    float a1 = (p[4] + p[5]) + (p[6] + p[7]);
    float a2 = (p[8] + p[9]) + (p[10] + p[11]);
    float a3 = (p[12] + p[13]) + (p[14] + p[15]);
    return (a0 + a1) + (a2 + a3);
}
__device__ __forceinline__ float tmax16(const float (&p)[16]) {
    float a0 = fmaxf(fmaxf(p[0], p[1]), fmaxf(p[2], p[3]));
    float a1 = fmaxf(fmaxf(p[4], p[5]), fmaxf(p[6], p[7]));
    float a2 = fmaxf(fmaxf(p[8], p[9]), fmaxf(p[10], p[11]));
    float a3 = fmaxf(fmaxf(p[12], p[13]), fmaxf(p[14], p[15]));
    return fmaxf(fmaxf(a0, a1), fmaxf(a2, a3));
}
// per-warp structured-P detection (all 32 lanes, before any divergence)
__device__ __forceinline__ int detect_str(const float* __restrict__ P, float& c1, float& c2) {
    c1 = __ldg(P); c2 = __ldg(P + 1);
    int lane = threadIdx.x & 31;
    int ok = 1;
#pragma unroll
    for (int i = 0; i < 8; i++) {
        int idx = lane * 8 + i;
        float v = __ldg(P + idx);
        float e = ((idx & 15) == (idx >> 4)) ? c1 : c2;
        ok &= (fabsf(v - e) <= 1e-6f * fabsf(e) + 1e-30f) ? 1 : 0;
    }
    return __all_sync(0xffffffffu, ok);
}

// ---------------- K1a: structured-P chunk transfer matrix products ----------------
// Register-lean: no sP, no acc[16]. Shared-staged exp(B). 16 units per 256-thr block.
__global__ void __launch_bounds__(256) k_chunkprod_str(const float* __restrict__ logB,
                                                       const float* __restrict__ P,
                                                       int B, int T, int NC) {
    float c1, c2;
    if (!detect_str(P, c1, c2)) return;
    float dd = c1 - c2;

    __shared__ float sB[16][CHUNK_L * 16];
    int gtid = blockIdx.x * blockDim.x + threadIdx.x;
    int unit = gtid >> 4;
    int u = threadIdx.x >> 4;
    int lane = threadIdx.x & 15;
    unsigned hmask = 0xFFFFu << (threadIdx.x & 16);
    if (unit >= B * NC) return;
    int b = unit / NC, c = unit - b * NC;
    int t0 = c * CHUNK_L + 1;
    int t1 = min((c + 1) * CHUNK_L, T - 1);
    int nst = t1 - t0 + 1;
    float* bu = sB[u];

    // stage exp(logB) for this unit's steps
    const float* lb = logB + ((size_t)b * T + t0) * 16;
    for (int i = lane; i < nst * 16; i += 16) bu[i] = __expf(lb[i]);
    __syncwarp(hmask);

    float m[16];
#pragma unroll
    for (int k = 0; k < 16; k++) m[k] = (k == lane) ? 1.f : 0.f;

    for (int i = 0; i < nst; i++) {
        float cr = c2 * tsum16(m);
        const float* bi = bu + i * 16;
#pragma unroll
        for (int k = 0; k < 16; k++) m[k] = fmaf(dd, m[k], cr) * bi[k];
        if ((i & 7) == 7) {
            float inv = __fdividef(1.f, bflymax16(tmax16(m), hmask));
#pragma unroll
            for (int k = 0; k < 16; k++) m[k] *= inv;
        }
    }
    float inv = __fdividef(1.f, bflymax16(tmax16(m), hmask));
    float4* G4 = reinterpret_cast<float4*>(g_G + (size_t)unit * 256 + lane * 16);
#pragma unroll
    for (int i = 0; i < 4; i++)
        G4[i] = make_float4(m[4 * i] * inv, m[4 * i + 1] * inv,
                            m[4 * i + 2] * inv, m[4 * i + 3] * inv);
}

// ---------------- K1b: generic-P fallback (early-exits when P is structured) ----------------
__global__ void k_chunkprod_gen(const float* __restrict__ logB, const float* __restrict__ P,
                                int B, int T, int NC) {
    float c1, c2;
    if (detect_str(P, c1, c2)) return;
    __shared__ float sP[256];
    sP[threadIdx.x] = P[threadIdx.x];
    __syncthreads();

    int gtid = blockIdx.x * blockDim.x + threadIdx.x;
    int unit = gtid >> 4;
    int lane = threadIdx.x & 15;
    unsigned hmask = 0xFFFFu << (threadIdx.x & 16);
    if (unit >= B * NC) return;
    int b = unit / NC, c = unit - b * NC;
    int t0 = c * CHUNK_L + 1;
    int t1 = min((c + 1) * CHUNK_L, T - 1);
    const float* lb = logB + (size_t)b * T * 16;

    float m[16];
#pragma unroll
    for (int k = 0; k < 16; k++) m[k] = (k == lane) ? 1.f : 0.f;

    int cnt = 0;
    for (int t = t0; t <= t1; t++) {
        float bvk = __expf(lb[(size_t)t * 16 + lane]);
        float acc[16];
#pragma unroll
        for (int k = 0; k < 16; k++) acc[k] = 0.f;
#pragma unroll
        for (int l = 0; l < 16; l++) {
            float ml = m[l];
#pragma unroll
            for (int k = 0; k < 16; k++) acc[k] = fmaf(ml, sP[l * 16 + k], acc[k]);
        }
#pragma unroll
        for (int k = 0; k < 16; k++)
            m[k] = acc[k] * __shfl_sync(0xffffffffu, bvk, k, 16);
        if ((++cnt & 7) == 0) {
            float inv = __fdividef(1.f, bflymax16(tmax16(m), hmask));
#pragma unroll
            for (int k = 0; k < 16; k++) m[k] *= inv;
        }
    }
    float inv = __fdividef(1.f, bflymax16(tmax16(m), hmask));
    float4* G4 = reinterpret_cast<float4*>(g_G + (size_t)unit * 256 + lane * 16);
#pragma unroll
    for (int i = 0; i < 4; i++)
        G4[i] = make_float4(m[4 * i] * inv, m[4 * i + 1] * inv,
                            m[4 * i + 2] * inv, m[4 * i + 3] * inv);
}

// ---------------- K2: sequential boundary chains (per batch), prefetched ----------------
__global__ void k_bound(const float* __restrict__ logB, int B, int T, int NC) {
    int b = blockIdx.x;
    int w = threadIdx.x >> 5;
    int lane = threadIdx.x & 31;
    int k = lane & 15;
    const unsigned F = 0xffffffffu;
    const float* Gb = g_G + (size_t)b * NC * 256;

    if (w == 0) {
        // forward: alpha_0 ~ exp(logB_0) (uniform prior cancels)
        float a = __expf(logB[(size_t)b * T * 16 + k]);
        { float Z = bflysum16(a, F); a *= __fdividef(1.f, Z); }
        if (lane < 16) g_abound[(b * NC) * 16 + k] = a;
        if (NC < 2) return;
        float g[16], gn[16];
#pragma unroll
        for (int j = 0; j < 16; j++) g[j] = Gb[j * 16 + k];          // column k of G_0
        for (int c = 0; c < NC - 1; c++) {
            const float* Gn = Gb + (size_t)min(c + 1, NC - 2) * 256;  // prefetch next
#pragma unroll
            for (int j = 0; j < 16; j++) gn[j] = Gn[j * 16 + k];
            float p[16];
#pragma unroll
            for (int j = 0; j < 16; j++) p[j] = __shfl_sync(F, a, j, 16) * g[j];
            float s = tsum16(p);
            float Z = bflysum16(s, F);
            a = s * __fdividef(1.f, Z);
            if (lane < 16) g_abound[(b * NC + c + 1) * 16 + k] = a;
#pragma unroll
            for (int j = 0; j < 16; j++) g[j] = gn[j];
        }
    } else {
        // backward: bbound[NC-1] = normalize(G_{NC-1} * 1); chain down with G_c rows
        float h[16], hn[16];
        {
            const float4* Gr = reinterpret_cast<const float4*>(Gb + (size_t)(NC - 1) * 256 + k * 16);
#pragma unroll
            for (int i = 0; i < 4; i++) {
                float4 q = Gr[i];
                h[4 * i] = q.x; h[4 * i + 1] = q.y; h[4 * i + 2] = q.z; h[4 * i + 3] = q.w;
            }
        }
        float bv = tsum16(h);
        { float Z = bflysum16(bv, F); bv *= __fdividef(1.f, Z); }
        if (lane < 16) g_bbound[(b * NC + NC - 1) * 16 + k] = bv;
        if (NC < 2) return;
        {
            const float4* Gr = reinterpret_cast<const float4*>(Gb + (size_t)(NC - 2) * 256 + k * 16);
#pragma unroll
            for (int i = 0; i < 4; i++) {
                float4 q = Gr[i];
                h[4 * i] = q.x; h[4 * i + 1] = q.y; h[4 * i + 2] = q.z; h[4 * i + 3] = q.w;
            }
        }
        for (int c = NC - 2; c >= 0; c--) {
            const float4* Gr = reinterpret_cast<const float4*>(Gb + (size_t)max(c - 1, 0) * 256 + k * 16);
#pragma unroll
            for (int i = 0; i < 4; i++) {
                float4 q = Gr[i];
                hn[4 * i] = q.x; hn[4 * i + 1] = q.y; hn[4 * i + 2] = q.z; hn[4 * i + 3] = q.w;
            }
            float p[16];
#pragma unroll
            for (int kk = 0; kk < 16; kk++) p[kk] = h[kk] * __shfl_sync(F, bv, kk, 16);
            float s = tsum16(p);
            float Z = bflysum16(s, F);
            bv = s * __fdividef(1.f, Z);
            if (lane < 16) g_bbound[(b * NC + c) * 16 + k] = bv;
#pragma unroll
            for (int kk = 0; kk < 16; kk++) h[kk] = hn[kk];
        }
    }
}

// ---------------- K3: fused backward-replay + forward-replay + gamma + xi ----------------
// One warp per (batch,chunk). Halves duplicate the 16-state vectors.
__global__ void __launch_bounds__(128) k_fused(const float* __restrict__ logB,
                                               const float* __restrict__ P,
                                               int B, int T, int NC,
                                               float* __restrict__ gamma,
                                               float* __restrict__ xi) {
    __shared__ float shB[4][(CHUNK_L + 1) * 16];
    __shared__ float shT[4][(CHUNK_L + 1) * 16];
    __shared__ float sP[256];
    sP[threadIdx.x] = P[threadIdx.x];
    sP[threadIdx.x + 128] = P[threadIdx.x + 128];
    float c1, c2;
    int str = detect_str(P, c1, c2);
    __syncthreads();
    float dd = c1 - c2;
    const unsigned F = 0xffffffffu;

    int wid = threadIdx.x >> 5;
    int lane = threadIdx.x & 31;
    int k = lane & 15;
    int half = lane >> 4;
    int unit = blockIdx.x * 4 + wid;
    if (unit >= B * NC) return;
    int b = unit / NC, c = unit - b * NC;
    int s = c * CHUNK_L, e = min(s + CHUNK_L, T);
    int n = e - s;
    float* Bw = shB[wid];
    float* Tw = shT[wid];

    // ---- phase A: load + exp chunk rows s..min(e,T-1) into shared ----
    int rows = min(e, T - 1) - s + 1;
    const float4* src = reinterpret_cast<const float4*>(logB) + ((size_t)b * T + s) * 4;
    for (int i = lane; i < rows * 4; i += 32) {
        float4 v = src[i];
        reinterpret_cast<float4*>(Bw)[i] =
            make_float4(__expf(v.x), __expf(v.y), __expf(v.z), __expf(v.w));
    }
    __syncwarp();

    // ---- phase B: backward replay into shared ----
    float bcur; int tstart;
    if (c == NC - 1) {
        bcur = 1.f;
        if (half == 0) Tw[(n - 1) * 16 + k] = 1.f;
        tstart = e - 2;
    } else {
        bcur = g_bbound[(b * NC + c + 1) * 16 + k];
        if (half == 0) Tw[n * 16 + k] = bcur;
        tstart = e - 1;
    }
    for (int t = tstart; t >= s; t--) {
        float Bn = Bw[(t + 1 - s) * 16 + k];
        float w = Bn * bcur;
        float W = bflysum16(w, F);
        float iW = __fdividef(1.f, W);
        float nb;
        if (str) {
            nb = fmaf(dd, w * iW, c2);
        } else {
            float acc = 0.f;
#pragma unroll
            for (int kk = 0; kk < 16; kk++)
                acc = fmaf(sP[k * 16 + kk], __shfl_sync(F, w, kk, 16), acc);
            nb = acc * iW;
        }
        if (half == 0) Tw[(t - s) * 16 + k] = nb;
        bcur = nb;
    }
    __syncwarp();

    // ---- phase C: forward replay, emit gamma + xi ----
    float alpha = g_abound[(b * NC + c) * 16 + k];
    { float Z = bflysum16(alpha, F); alpha *= __fdividef(1.f, Z); }
    int jw = lane >> 1;          // xi row this lane writes
    int hk = (lane & 1) * 8;     // xi column base
    float pvv[8];
#pragma unroll
    for (int i = 0; i < 8; i++)
        pvv[i] = str ? ((jw == hk + i) ? c1 : c2) : sP[jw * 16 + hk + i];

    for (int t = s; t < e; t++) {
        float beta = Tw[(t - s) * 16 + k];
        float ab = alpha * beta;
        float Zg = bflysum16(ab, F);
        if (half == 0) gamma[((size_t)b * T + t) * 16 + k] = ab * __fdividef(1.f, Zg);

        if (t < T - 1) {
            float Be = Bw[(t + 1 - s) * 16 + k];
            float bn = Tw[(t + 1 - s) * 16 + k];
            float w = Be * bn;
            float u;
            if (str) {
                u = fmaf(dd, alpha, c2);            // needs sum(alpha)==1 (maintained)
            } else {
                u = 0.f;
#pragma unroll
                for (int j = 0; j < 16; j++)
                    u = fmaf(__shfl_sync(F, alpha, j, 16), sP[j * 16 + k], u);
            }
            float Zx = bflysum16(u * w, F);
            float q = w * __fdividef(1.f, Zx);
            float aj = __shfl_sync(F, alpha, jw, 16);
            float v0[8];
#pragma unroll
            for (int i = 0; i < 8; i++)
                v0[i] = aj * pvv[i] * __shfl_sync(F, q, hk + i, 16);
            float4* xo = reinterpret_cast<float4*>(
                xi + ((size_t)b * (T - 1) + t) * 256 + jw * 16 + hk);
            xo[0] = make_float4(v0[0], v0[1], v0[2], v0[3]);
            xo[1] = make_float4(v0[4], v0[5], v0[6], v0[7]);

            float an = u * Be;
            float Sn = bflysum16(an, F);
            alpha = an * __fdividef(1.f, Sn);
        }
    }
}

// ---------------- host ----------------
extern "C" void kernel_launch(void* const* d_in, const int* in_sizes, int n_in,
                              void* d_out, int out_size) {
    const float* logB = (const float*)d_in[0];
    const float* P    = (const float*)d_in[1];
    long long nB = in_sizes[0];            // B*T*16
    long long BT = nB / 16;
    long long xiE = (long long)out_size - nB;
    int B = (int)(BT - xiE / 256);
    int T = (int)(BT / B);
    int NC = (T + CHUNK_L - 1) / CHUNK_L;

    float* gamma = (float*)d_out;
    float* xi = gamma + (size_t)B * T * 16;

    int units = B * NC;
    int cpb = (units * 16 + 255) / 256;
    k_chunkprod_str<<<cpb, 256>>>(logB, P, B, T, NC);
    k_chunkprod_gen<<<cpb, 256>>>(logB, P, B, T, NC);
    k_bound<<<B, 64>>>(logB, B, T, NC);
    k_fused<<<(units + 3) / 4, 128>>>(logB, P, B, T, NC, gamma, xi);
    (void)n_in;
}